// round 2
// baseline (speedup 1.0000x reference)
#include <cuda_runtime.h>
#include <cuda_bf16.h>

// ResidualizeEMA: out[b,t,g] = sum_f x[b,t,f]*W[f,g] + bias[g] + last[b,g]
// last[b,g] = sum_t w[t]*x[b,t,g],  w[t] = 0.2*0.8^(T-1-t)  (w[0]=0.8^(T-1))
// Weights for T-1-t >= 512 underflow to exactly 0 in fp32 -> truncate EMA to
// last 512 timesteps (bit-identical weight set vs reference fp32 weights).

#define T_DIM 2048
#define F_DIM 256
#define B_DIM 64
#define EMA_STEPS 512

__device__ float g_lastpb[B_DIM * F_DIM];  // last[b,g] + bias[g]

// ---------------------------------------------------------------------------
// Kernel 1: EMA over last EMA_STEPS timesteps + fold in bias.
// One block per batch, one thread per feature. Coalesced across f.
// ---------------------------------------------------------------------------
__global__ void __launch_bounds__(256) ema_kernel(const float* __restrict__ x,
                                                  const float* __restrict__ bias) {
    const int b = blockIdx.x;
    const int f = threadIdx.x;
    const float* p = x + ((long)b * T_DIM + (T_DIM - 1)) * F_DIM + f;
    float acc = 0.0f;
    float w = 0.2f;  // weight at t = T-1
    #pragma unroll 8
    for (int i = 0; i < EMA_STEPS; i++) {
        acc = fmaf(w, *p, acc);
        w *= 0.8f;
        p -= F_DIM;
    }
    g_lastpb[b * F_DIM + f] = acc + bias[f];
}

// ---------------------------------------------------------------------------
// Kernel 2: SGEMM  C[M,256] = A[M,256] * W[256,256]  + epilogue (lastpb).
// M = B*T = 131072. Tiles: BM=128, BN=128, BK=32. 256 threads, 8x8 per thread.
// A tile stored transposed in smem with +1 padding (conflict-free STS/LDS).
// B columns read as two float4 groups (tx*4 and 64+tx*4) -> conflict-free LDS.128.
// ---------------------------------------------------------------------------
__global__ void __launch_bounds__(256, 2) gemm_kernel(const float* __restrict__ A,
                                                      const float* __restrict__ W,
                                                      float* __restrict__ C) {
    __shared__ float As[32][129];   // [k][m], padded
    __shared__ float Bs[32][128];   // [k][n]

    const int tid = threadIdx.x;
    const int tx = tid & 15;        // 0..15 -> column groups
    const int ty = tid >> 4;        // 0..15 -> row groups
    const long rowBase = (long)blockIdx.y * 128;
    const int  colBase = blockIdx.x * 128;

    // Global load mapping
    const int aRow = tid >> 3;          // 0..31
    const int aCol = (tid & 7) << 2;    // 0,4,...,28
    const int bRow = tid >> 5;          // 0..7
    const int bCol = (tid & 31) << 2;   // 0,4,...,124

    const float* Aptr = A + (rowBase + aRow) * 256 + aCol;
    const float* Wptr = W + bRow * 256 + colBase + bCol;

    float acc[8][8];
    #pragma unroll
    for (int i = 0; i < 8; i++)
        #pragma unroll
        for (int j = 0; j < 8; j++) acc[i][j] = 0.0f;

    for (int k0 = 0; k0 < 256; k0 += 32) {
        // Load A tile (128 rows x 32 k) transposed into As, W tile into Bs.
        #pragma unroll
        for (int q = 0; q < 4; q++) {
            float4 av = *(const float4*)(Aptr + (long)(q * 32) * 256 + k0);
            As[aCol + 0][aRow + q * 32] = av.x;
            As[aCol + 1][aRow + q * 32] = av.y;
            As[aCol + 2][aRow + q * 32] = av.z;
            As[aCol + 3][aRow + q * 32] = av.w;
            float4 wv = *(const float4*)(Wptr + (k0 + q * 8) * 256);
            *(float4*)&Bs[bRow + q * 8][bCol] = wv;
        }
        __syncthreads();

        #pragma unroll
        for (int k = 0; k < 32; k++) {
            float ra[8], rb[8];
            #pragma unroll
            for (int i = 0; i < 8; i++) ra[i] = As[k][ty * 8 + i];
            *(float4*)&rb[0] = *(const float4*)&Bs[k][tx * 4];
            *(float4*)&rb[4] = *(const float4*)&Bs[k][64 + tx * 4];
            #pragma unroll
            for (int i = 0; i < 8; i++)
                #pragma unroll
                for (int j = 0; j < 8; j++)
                    acc[i][j] = fmaf(ra[i], rb[j], acc[i][j]);
        }
        __syncthreads();
    }

    // Epilogue: add lastpb[b, col]. All 128 rows of this block share one batch
    // (T=2048 divisible by BM=128).
    const int bIdx = (int)(rowBase >> 11);  // rowBase / 2048
    const float* lp = g_lastpb + bIdx * 256 + colBase;
    const float4 l0 = *(const float4*)(lp + tx * 4);
    const float4 l1 = *(const float4*)(lp + 64 + tx * 4);

    #pragma unroll
    for (int i = 0; i < 8; i++) {
        float* crow = C + (rowBase + ty * 8 + i) * 256 + colBase;
        float4 o0, o1;
        o0.x = acc[i][0] + l0.x; o0.y = acc[i][1] + l0.y;
        o0.z = acc[i][2] + l0.z; o0.w = acc[i][3] + l0.w;
        o1.x = acc[i][4] + l1.x; o1.y = acc[i][5] + l1.y;
        o1.z = acc[i][6] + l1.z; o1.w = acc[i][7] + l1.w;
        *(float4*)(crow + tx * 4)      = o0;
        *(float4*)(crow + 64 + tx * 4) = o1;
    }
}

extern "C" void kernel_launch(void* const* d_in, const int* in_sizes, int n_in,
                              void* d_out, int out_size) {
    const float* x    = (const float*)d_in[0];  // [64, 2048, 256]
    const float* W    = (const float*)d_in[1];  // [256, 256]
    const float* bias = (const float*)d_in[2];  // [256]
    float* out = (float*)d_out;                 // [64, 2048, 256]

    ema_kernel<<<B_DIM, 256>>>(x, bias);

    dim3 grid(2, (B_DIM * T_DIM) / 128);        // (N/128, M/128) = (2, 1024)
    gemm_kernel<<<grid, 256>>>(x, W, out);
}

// round 7
// speedup vs baseline: 1.7093x; 1.7093x over previous
#include <cuda_runtime.h>
#include <cuda_bf16.h>
#include <cstdint>

#define T_DIM 2048
#define F_DIM 256
#define B_DIM 64
#define BM 128
#define BN 128
#define BK 32
#define NSEG 4

// ---------------- device scratch (no runtime allocs) ----------------
__device__ float g_part[B_DIM * NSEG * F_DIM];                  // EMA segment partials
__device__ __align__(16) __nv_bfloat16 g_Whi[F_DIM * F_DIM];    // Wt[n][k] hi
__device__ __align__(16) __nv_bfloat16 g_Wlo[F_DIM * F_DIM];    // Wt[n][k] lo

__device__ __forceinline__ uint32_t smem_u32(const void* p) {
    uint32_t a;
    asm("{ .reg .u64 t; cvta.to.shared.u64 t, %1; cvt.u32.u64 %0, t; }" : "=r"(a) : "l"(p));
    return a;
}

#define LDSM4(r, addr)                                                              \
    asm volatile("ldmatrix.sync.aligned.m8n8.x4.shared.b16 {%0,%1,%2,%3}, [%4];"    \
                 : "=r"((r)[0]), "=r"((r)[1]), "=r"((r)[2]), "=r"((r)[3])           \
                 : "r"(addr))

#define MMA_BF16(d, a, b0, b1)                                                      \
    asm volatile("mma.sync.aligned.m16n8k16.row.col.f32.bf16.bf16.f32 "             \
                 "{%0,%1,%2,%3}, {%4,%5,%6,%7}, {%8,%9}, {%0,%1,%2,%3};"            \
                 : "+f"((d)[0]), "+f"((d)[1]), "+f"((d)[2]), "+f"((d)[3])           \
                 : "r"((a)[0]), "r"((a)[1]), "r"((a)[2]), "r"((a)[3]),              \
                   "r"(b0), "r"(b1))

#define CPA16(sdst, gsrc)                                                           \
    asm volatile("cp.async.cg.shared.global [%0], [%1], 16;"                        \
                 :: "r"((uint32_t)(sdst)), "l"(gsrc) : "memory")
#define CPA_COMMIT() asm volatile("cp.async.commit_group;" ::: "memory")
#define CPA_WAIT0()  asm volatile("cp.async.wait_group 0;" ::: "memory")

// smem stage layout (32KB/stage): Ahi 8K | Alo 8K | Bhi 8K | Blo 8K; 2 stages; lastpb 1K
#define OFF_AHI 0
#define OFF_ALO 8192
#define OFF_BHI 16384
#define OFF_BLO 24576
#define STAGE_BYTES 32768
#define OFF_LAST 65536
#define SMEM_BYTES (65536 + 1024 + 256)

// tile swizzle: row r (64B of 4x16B chunks): chunk slot = chunk ^ ((r>>1)&3)
__device__ __forceinline__ uint32_t tile_off(int r, int chunk) {
    return (uint32_t)(r * 64 + ((chunk ^ ((r >> 1) & 3)) << 4));
}

// ---------------------------------------------------------------------------
// W pre-convert: Wt[n][k] = W[k][n] split to bf16 hi/lo.
// ---------------------------------------------------------------------------
__global__ void __launch_bounds__(256) wconv_kernel(const float* __restrict__ W) {
    int idx = blockIdx.x * 256 + threadIdx.x;   // 65536
    int k = idx >> 8, n = idx & 255;
    float v = W[k * 256 + n];
    __nv_bfloat16 hi = __float2bfloat16(v);
    __nv_bfloat16 lo = __float2bfloat16(v - __bfloat162float(hi));
    g_Whi[n * 256 + k] = hi;
    g_Wlo[n * 256 + k] = lo;
}

// ---------------------------------------------------------------------------
// EMA segment partials: seg s covers distances d = s*128 .. s*128+127 from T-1.
// weight(d) = 0.2*0.8^d; d>=512 underflows to 0 in fp32 (matches reference).
// ---------------------------------------------------------------------------
__global__ void __launch_bounds__(256) ema_part_kernel(const float* __restrict__ x) {
    const int b = blockIdx.x, s = blockIdx.y, f = threadIdx.x;
    float c128 = 0.8f;
    #pragma unroll
    for (int i = 0; i < 7; i++) c128 *= c128;  // 0.8^128
    float w = 0.2f;
    for (int i = 0; i < s; i++) w *= c128;
    const float* p = x + ((long)b * T_DIM + (T_DIM - 1 - s * 128)) * F_DIM + f;
    float acc = 0.0f;
    #pragma unroll 8
    for (int i = 0; i < 128; i++) {
        acc = fmaf(w, *p, acc);
        w *= 0.8f;
        p -= F_DIM;
    }
    g_part[(b * NSEG + s) * F_DIM + f] = acc;
}

// ---------------------------------------------------------------------------
// GEMM via mma.sync bf16 (3-product fp32 emulation) + fused EMA/bias epilogue.
// ---------------------------------------------------------------------------
__global__ void __launch_bounds__(256) gemm_mma_kernel(const float* __restrict__ x,
                                                       const float* __restrict__ bias,
                                                       float* __restrict__ out) {
    extern __shared__ char smraw[];
    char* sb = (char*)(((uintptr_t)smraw + 127) & ~(uintptr_t)127);
    const uint32_t sbase = smem_u32(sb);
    const int tid = threadIdx.x;
    const int lane = tid & 31, wid = tid >> 5;
    const int wm = wid & 1, wn = wid >> 1;          // warp grid 2(m) x 4(n)
    const long rowBase = (long)blockIdx.y * BM;
    const int nBase = blockIdx.x * BN;

    // lastpb[f] = bias[f] + sum_s g_part[b][s][f]
    {
        const int bidx = (int)(rowBase >> 11);
        float v = bias[tid];
        #pragma unroll
        for (int s = 0; s < NSEG; s++) v += g_part[(bidx * NSEG + s) * F_DIM + tid];
        *(float*)(sb + OFF_LAST + tid * 4) = v;
    }

    // ---- A load mapping: thread -> (row, k-half), 4 float4 per stage ----
    const int arow = tid & 127;
    const int akc  = tid >> 7;                       // 0..1 (16 k each)
    const float* aptr = x + (rowBase + arow) * 256 + akc * 16;
    const uint32_t a_sts0 = tile_off(arow, akc * 2);
    const uint32_t a_sts1 = tile_off(arow, akc * 2 + 1);

    // ---- B cp.async mapping: thread -> (n-row, chunk pair) ----
    const int bn  = tid >> 1;                        // 0..127
    const int bc0 = (tid & 1) * 2;                   // 0 or 2
    const __nv_bfloat16* bsrc_hi = g_Whi + (nBase + bn) * 256 + bc0 * 8;
    const __nv_bfloat16* bsrc_lo = g_Wlo + (nBase + bn) * 256 + bc0 * 8;
    const uint32_t b_dst0 = tile_off(bn, bc0);
    const uint32_t b_dst1 = tile_off(bn, bc0 + 1);

    // ---- ldmatrix lane address components ----
    const int ar = lane & 15;                        // row within fragment
    const int ac = lane >> 4;                        // chunk offset (0/1)

    float acc[4][4][4];
    #pragma unroll
    for (int i = 0; i < 4; i++)
        #pragma unroll
        for (int j = 0; j < 4; j++)
            #pragma unroll
            for (int q = 0; q < 4; q++) acc[i][j][q] = 0.0f;

    float4 xv[4];

    // ---- prologue: stage 0 ----
    #pragma unroll
    for (int i = 0; i < 4; i++) xv[i] = *(const float4*)(aptr + i * 4);
    {
        const uint32_t sd = sbase;
        CPA16(sd + OFF_BHI + b_dst0, (const char*)bsrc_hi);
        CPA16(sd + OFF_BHI + b_dst1, (const char*)bsrc_hi + 16);
        CPA16(sd + OFF_BLO + b_dst0, (const char*)bsrc_lo);
        CPA16(sd + OFF_BLO + b_dst1, (const char*)bsrc_lo + 16);
        CPA_COMMIT();
    }
    {
        uint32_t h[8], l[8];
        const float* fv = (const float*)xv;
        #pragma unroll
        for (int j = 0; j < 8; j++) {
            __nv_bfloat162 hh, ll;
            hh.x = __float2bfloat16(fv[2 * j]);
            hh.y = __float2bfloat16(fv[2 * j + 1]);
            ll.x = __float2bfloat16(fv[2 * j] - __bfloat162float(hh.x));
            ll.y = __float2bfloat16(fv[2 * j + 1] - __bfloat162float(hh.y));
            h[j] = *(uint32_t*)&hh; l[j] = *(uint32_t*)&ll;
        }
        *(uint4*)(sb + OFF_AHI + a_sts0) = make_uint4(h[0], h[1], h[2], h[3]);
        *(uint4*)(sb + OFF_AHI + a_sts1) = make_uint4(h[4], h[5], h[6], h[7]);
        *(uint4*)(sb + OFF_ALO + a_sts0) = make_uint4(l[0], l[1], l[2], l[3]);
        *(uint4*)(sb + OFF_ALO + a_sts1) = make_uint4(l[4], l[5], l[6], l[7]);
    }
    CPA_WAIT0();
    __syncthreads();

    // ---- mainloop: 8 K-iters of BK=32, double-buffered ----
    #pragma unroll 1
    for (int c = 0; c < 8; c++) {
        const uint32_t cur = (uint32_t)(c & 1) * STAGE_BYTES;
        const uint32_t nxt = (uint32_t)((c + 1) & 1) * STAGE_BYTES;

        if (c < 7) {
            #pragma unroll
            for (int i = 0; i < 4; i++) xv[i] = *(const float4*)(aptr + (c + 1) * 32 + i * 4);
            const uint32_t sd = sbase + nxt;
            const int ko = (c + 1) * 32;
            CPA16(sd + OFF_BHI + b_dst0, (const char*)(bsrc_hi + ko));
            CPA16(sd + OFF_BHI + b_dst1, (const char*)(bsrc_hi + ko) + 16);
            CPA16(sd + OFF_BLO + b_dst0, (const char*)(bsrc_lo + ko));
            CPA16(sd + OFF_BLO + b_dst1, (const char*)(bsrc_lo + ko) + 16);
            CPA_COMMIT();
        }

        // compute current stage
        #pragma unroll
        for (int ks = 0; ks < 2; ks++) {
            uint32_t ah[4][4], al[4][4], bh[2][4], bl[2][4];
            const int chunk = ks * 2 + ac;
            #pragma unroll
            for (int mf = 0; mf < 4; mf++) {
                const int r = wm * 64 + mf * 16 + ar;
                const uint32_t o = tile_off(r, chunk);
                LDSM4(ah[mf], sbase + cur + OFF_AHI + o);
                LDSM4(al[mf], sbase + cur + OFF_ALO + o);
            }
            #pragma unroll
            for (int nb = 0; nb < 2; nb++) {
                const int r = wn * 32 + nb * 16 + ar;
                const uint32_t o = tile_off(r, chunk);
                LDSM4(bh[nb], sbase + cur + OFF_BHI + o);
                LDSM4(bl[nb], sbase + cur + OFF_BLO + o);
            }
            #pragma unroll
            for (int mf = 0; mf < 4; mf++)
                #pragma unroll
                for (int nf = 0; nf < 4; nf++) {
                    const int nb = nf >> 1, p = nf & 1;
                    MMA_BF16(acc[mf][nf], ah[mf], bh[nb][p], bh[nb][2 + p]);
                    MMA_BF16(acc[mf][nf], al[mf], bh[nb][p], bh[nb][2 + p]);
                    MMA_BF16(acc[mf][nf], ah[mf], bl[nb][p], bl[nb][2 + p]);
                }
        }

        if (c < 7) {
            uint32_t h[8], l[8];
            const float* fv = (const float*)xv;
            #pragma unroll
            for (int j = 0; j < 8; j++) {
                __nv_bfloat162 hh, ll;
                hh.x = __float2bfloat16(fv[2 * j]);
                hh.y = __float2bfloat16(fv[2 * j + 1]);
                ll.x = __float2bfloat16(fv[2 * j] - __bfloat162float(hh.x));
                ll.y = __float2bfloat16(fv[2 * j + 1] - __bfloat162float(hh.y));
                h[j] = *(uint32_t*)&hh; l[j] = *(uint32_t*)&ll;
            }
            char* dst = sb + nxt;
            *(uint4*)(dst + OFF_AHI + a_sts0) = make_uint4(h[0], h[1], h[2], h[3]);
            *(uint4*)(dst + OFF_AHI + a_sts1) = make_uint4(h[4], h[5], h[6], h[7]);
            *(uint4*)(dst + OFF_ALO + a_sts0) = make_uint4(l[0], l[1], l[2], l[3]);
            *(uint4*)(dst + OFF_ALO + a_sts1) = make_uint4(l[4], l[5], l[6], l[7]);
            CPA_WAIT0();
        }
        __syncthreads();
    }

    // ---- epilogue: add lastpb, direct STG.64 ----
    const float* sl = (const float*)(sb + OFF_LAST);
    float lp[4][2];
    #pragma unroll
    for (int nf = 0; nf < 4; nf++) {
        const int cc = nBase + wn * 32 + nf * 8 + (lane & 3) * 2;   // FIX: + nBase
        lp[nf][0] = sl[cc];
        lp[nf][1] = sl[cc + 1];
    }
    #pragma unroll
    for (int mf = 0; mf < 4; mf++) {
        const long r0 = rowBase + wm * 64 + mf * 16 + (lane >> 2);
        #pragma unroll
        for (int nf = 0; nf < 4; nf++) {
            const int cc = nBase + wn * 32 + nf * 8 + (lane & 3) * 2;
            float2 v0 = make_float2(acc[mf][nf][0] + lp[nf][0], acc[mf][nf][1] + lp[nf][1]);
            float2 v1 = make_float2(acc[mf][nf][2] + lp[nf][0], acc[mf][nf][3] + lp[nf][1]);
            *(float2*)(out + r0 * 256 + cc)       = v0;
            *(float2*)(out + (r0 + 8) * 256 + cc) = v1;
        }
    }
}

extern "C" void kernel_launch(void* const* d_in, const int* in_sizes, int n_in,
                              void* d_out, int out_size) {
    const float* x    = (const float*)d_in[0];  // [64, 2048, 256]
    const float* W    = (const float*)d_in[1];  // [256, 256]
    const float* bias = (const float*)d_in[2];  // [256]
    float* out = (float*)d_out;                 // [64, 2048, 256]

    cudaFuncSetAttribute(gemm_mma_kernel, cudaFuncAttributeMaxDynamicSharedMemorySize, SMEM_BYTES);

    wconv_kernel<<<256, 256>>>(W);
    ema_part_kernel<<<dim3(B_DIM, NSEG), 256>>>(x);
    gemm_mma_kernel<<<dim3(2, (B_DIM * T_DIM) / BM), 256, SMEM_BYTES>>>(x, bias, out);
}

// round 8
// speedup vs baseline: 2.4520x; 1.4345x over previous
#include <cuda_runtime.h>
#include <cuda_fp16.h>
#include <cstdint>

#define T_DIM 2048
#define F_DIM 256
#define B_DIM 64
#define BM 128
#define BN 128
#define NSEG 4

// ---------------- device scratch (no runtime allocs) ----------------
__device__ float g_part[B_DIM * NSEG * F_DIM];          // EMA segment partials
__device__ __align__(16) __half g_Wh[F_DIM * F_DIM];    // Wt[n][k] fp16

__device__ __forceinline__ uint32_t smem_u32(const void* p) {
    uint32_t a;
    asm("{ .reg .u64 t; cvta.to.shared.u64 t, %1; cvt.u32.u64 %0, t; }" : "=r"(a) : "l"(p));
    return a;
}

#define LDSM4(r, addr)                                                              \
    asm volatile("ldmatrix.sync.aligned.m8n8.x4.shared.b16 {%0,%1,%2,%3}, [%4];"    \
                 : "=r"((r)[0]), "=r"((r)[1]), "=r"((r)[2]), "=r"((r)[3])           \
                 : "r"(addr))

#define MMA_F16(d, a, b0, b1)                                                       \
    asm volatile("mma.sync.aligned.m16n8k16.row.col.f32.f16.f16.f32 "               \
                 "{%0,%1,%2,%3}, {%4,%5,%6,%7}, {%8,%9}, {%0,%1,%2,%3};"            \
                 : "+f"((d)[0]), "+f"((d)[1]), "+f"((d)[2]), "+f"((d)[3])           \
                 : "r"((a)[0]), "r"((a)[1]), "r"((a)[2]), "r"((a)[3]),              \
                   "r"(b0), "r"(b1))

#define CPA16(sdst, gsrc)                                                           \
    asm volatile("cp.async.cg.shared.global [%0], [%1], 16;"                        \
                 :: "r"((uint32_t)(sdst)), "l"(gsrc) : "memory")
#define CPA_COMMIT() asm volatile("cp.async.commit_group;" ::: "memory")
#define CPA_WAIT0()  asm volatile("cp.async.wait_group 0;" ::: "memory")

// smem stage layout (16KB/stage): Ah 8K | Bh 8K; 2 stages; lastpb 1K
#define OFF_AH 0
#define OFF_BH 8192
#define STAGE_BYTES 16384
#define OFF_LAST 32768
#define SMEM_BYTES (32768 + 1024 + 256)

// tile swizzle: row r (64B = 4x16B chunks): chunk slot = chunk ^ ((r>>1)&3)
__device__ __forceinline__ uint32_t tile_off(int r, int chunk) {
    return (uint32_t)(r * 64 + ((chunk ^ ((r >> 1) & 3)) << 4));
}

// ---------------------------------------------------------------------------
// W pre-convert: Wt[n][k] = fp16(W[k][n]).
// ---------------------------------------------------------------------------
__global__ void __launch_bounds__(256) wconv_kernel(const float* __restrict__ W) {
    int idx = blockIdx.x * 256 + threadIdx.x;   // 65536
    int k = idx >> 8, n = idx & 255;
    g_Wh[n * 256 + k] = __float2half_rn(W[k * 256 + n]);
}

// ---------------------------------------------------------------------------
// EMA segment partials: seg s covers distances d = s*128 .. s*128+127 from T-1.
// weight(d) = 0.2*0.8^d; d>=512 underflows to 0 in fp32 (matches reference).
// ---------------------------------------------------------------------------
__global__ void __launch_bounds__(256) ema_part_kernel(const float* __restrict__ x) {
    const int b = blockIdx.x, s = blockIdx.y, f = threadIdx.x;
    float c128 = 0.8f;
    #pragma unroll
    for (int i = 0; i < 7; i++) c128 *= c128;  // 0.8^128
    float w = 0.2f;
    for (int i = 0; i < s; i++) w *= c128;
    const float* p = x + ((long)b * T_DIM + (T_DIM - 1 - s * 128)) * F_DIM + f;
    float acc = 0.0f;
    #pragma unroll 8
    for (int i = 0; i < 128; i++) {
        acc = fmaf(w, *p, acc);
        w *= 0.8f;
        p -= F_DIM;
    }
    g_part[(b * NSEG + s) * F_DIM + f] = acc;
}

// ---------------------------------------------------------------------------
// GEMM via single-product fp16 mma.sync + fused EMA/bias epilogue.
// ---------------------------------------------------------------------------
__global__ void __launch_bounds__(256) gemm_mma_kernel(const float* __restrict__ x,
                                                       const float* __restrict__ bias,
                                                       float* __restrict__ out) {
    extern __shared__ char smraw[];
    char* sb = (char*)(((uintptr_t)smraw + 127) & ~(uintptr_t)127);
    const uint32_t sbase = smem_u32(sb);
    const int tid = threadIdx.x;
    const int lane = tid & 31, wid = tid >> 5;
    const int wm = wid & 1, wn = wid >> 1;          // warp grid 2(m) x 4(n)
    const long rowBase = (long)blockIdx.y * BM;
    const int nBase = blockIdx.x * BN;

    // lastpb[f] = bias[f] + sum_s g_part[b][s][f]
    {
        const int bidx = (int)(rowBase >> 11);
        float v = bias[tid];
        #pragma unroll
        for (int s = 0; s < NSEG; s++) v += g_part[(bidx * NSEG + s) * F_DIM + tid];
        *(float*)(sb + OFF_LAST + tid * 4) = v;
    }

    // ---- A load mapping: thread -> (row, k-half of 16) ----
    const int arow = tid & 127;
    const int akc  = tid >> 7;                       // 0..1 (16 k each)
    const float* aptr = x + (rowBase + arow) * 256 + akc * 16;
    const uint32_t a_sts0 = tile_off(arow, akc * 2);      // 16B = 8 k fp16
    const uint32_t a_sts1 = tile_off(arow, akc * 2 + 1);

    // ---- B cp.async mapping: thread -> (n-row, 2 chunks) ----
    const int bn  = tid >> 1;                        // 0..127
    const int bc0 = (tid & 1) * 2;                   // 0 or 2
    const __half* bsrc = g_Wh + (nBase + bn) * 256 + bc0 * 8;
    const uint32_t b_dst0 = tile_off(bn, bc0);
    const uint32_t b_dst1 = tile_off(bn, bc0 + 1);

    // ---- ldmatrix lane address components ----
    const int ar = lane & 15;
    const int ac = lane >> 4;

    float acc[4][4][4];
    #pragma unroll
    for (int i = 0; i < 4; i++)
        #pragma unroll
        for (int j = 0; j < 4; j++)
            #pragma unroll
            for (int q = 0; q < 4; q++) acc[i][j][q] = 0.0f;

    float4 xv[4];

    // ---- prologue: stage 0 ----
    #pragma unroll
    for (int i = 0; i < 4; i++) xv[i] = *(const float4*)(aptr + i * 4);
    CPA16(sbase + OFF_BH + b_dst0, (const char*)bsrc);
    CPA16(sbase + OFF_BH + b_dst1, (const char*)bsrc + 16);
    CPA_COMMIT();
    {
        uint32_t h[8];
        const float* fv = (const float*)xv;
        #pragma unroll
        for (int j = 0; j < 8; j++) {
            __half2 hh = __floats2half2_rn(fv[2 * j], fv[2 * j + 1]);
            h[j] = *(uint32_t*)&hh;
        }
        *(uint4*)(sb + OFF_AH + a_sts0) = make_uint4(h[0], h[1], h[2], h[3]);
        *(uint4*)(sb + OFF_AH + a_sts1) = make_uint4(h[4], h[5], h[6], h[7]);
    }
    CPA_WAIT0();
    __syncthreads();

    // ---- mainloop: 8 K-iters of BK=32, double-buffered ----
    #pragma unroll 1
    for (int c = 0; c < 8; c++) {
        const uint32_t cur = (uint32_t)(c & 1) * STAGE_BYTES;
        const uint32_t nxt = (uint32_t)((c + 1) & 1) * STAGE_BYTES;

        if (c < 7) {
            #pragma unroll
            for (int i = 0; i < 4; i++) xv[i] = *(const float4*)(aptr + (c + 1) * 32 + i * 4);
            const int ko = (c + 1) * 32;
            CPA16(sbase + nxt + OFF_BH + b_dst0, (const char*)(bsrc + ko));
            CPA16(sbase + nxt + OFF_BH + b_dst1, (const char*)(bsrc + ko) + 16);
            CPA_COMMIT();
        }

        // compute current stage
        #pragma unroll
        for (int ks = 0; ks < 2; ks++) {
            uint32_t ah[4][4], bh[2][4];
            const int chunk = ks * 2 + ac;
            #pragma unroll
            for (int mf = 0; mf < 4; mf++) {
                const int r = wm * 64 + mf * 16 + ar;
                LDSM4(ah[mf], sbase + cur + OFF_AH + tile_off(r, chunk));
            }
            #pragma unroll
            for (int nb = 0; nb < 2; nb++) {
                const int r = wn * 32 + nb * 16 + ar;
                LDSM4(bh[nb], sbase + cur + OFF_BH + tile_off(r, chunk));
            }
            #pragma unroll
            for (int mf = 0; mf < 4; mf++)
                #pragma unroll
                for (int nf = 0; nf < 4; nf++) {
                    const int nb = nf >> 1, p = nf & 1;
                    MMA_F16(acc[mf][nf], ah[mf], bh[nb][p], bh[nb][2 + p]);
                }
        }

        if (c < 7) {
            uint32_t h[8];
            const float* fv = (const float*)xv;
            #pragma unroll
            for (int j = 0; j < 8; j++) {
                __half2 hh = __floats2half2_rn(fv[2 * j], fv[2 * j + 1]);
                h[j] = *(uint32_t*)&hh;
            }
            char* dst = sb + nxt;
            *(uint4*)(dst + OFF_AH + a_sts0) = make_uint4(h[0], h[1], h[2], h[3]);
            *(uint4*)(dst + OFF_AH + a_sts1) = make_uint4(h[4], h[5], h[6], h[7]);
            CPA_WAIT0();
        }
        __syncthreads();
    }

    // ---- epilogue: add lastpb, direct STG.64 ----
    const float* sl = (const float*)(sb + OFF_LAST);
    float lp[4][2];
    #pragma unroll
    for (int nf = 0; nf < 4; nf++) {
        const int cc = nBase + wn * 32 + nf * 8 + (lane & 3) * 2;
        lp[nf][0] = sl[cc];
        lp[nf][1] = sl[cc + 1];
    }
    #pragma unroll
    for (int mf = 0; mf < 4; mf++) {
        const long r0 = rowBase + wm * 64 + mf * 16 + (lane >> 2);
        #pragma unroll
        for (int nf = 0; nf < 4; nf++) {
            const int cc = nBase + wn * 32 + nf * 8 + (lane & 3) * 2;
            float2 v0 = make_float2(acc[mf][nf][0] + lp[nf][0], acc[mf][nf][1] + lp[nf][1]);
            float2 v1 = make_float2(acc[mf][nf][2] + lp[nf][0], acc[mf][nf][3] + lp[nf][1]);
            *(float2*)(out + r0 * 256 + cc)       = v0;
            *(float2*)(out + (r0 + 8) * 256 + cc) = v1;
        }
    }
}

extern "C" void kernel_launch(void* const* d_in, const int* in_sizes, int n_in,
                              void* d_out, int out_size) {
    const float* x    = (const float*)d_in[0];  // [64, 2048, 256]
    const float* W    = (const float*)d_in[1];  // [256, 256]
    const float* bias = (const float*)d_in[2];  // [256]
    float* out = (float*)d_out;                 // [64, 2048, 256]

    cudaFuncSetAttribute(gemm_mma_kernel, cudaFuncAttributeMaxDynamicSharedMemorySize, SMEM_BYTES);

    wconv_kernel<<<256, 256>>>(W);
    ema_part_kernel<<<dim3(B_DIM, NSEG), 256>>>(x);
    gemm_mma_kernel<<<dim3(2, (B_DIM * T_DIM) / BM), 256, SMEM_BYTES>>>(x, bias, out);
}